// round 7
// baseline (speedup 1.0000x reference)
#include <cuda_runtime.h>
#include <cuda_bf16.h>
#include <cstdint>

// Problem constants (fixed shapes from reference setup_inputs)
#define BB 4
#define NN 8192
#define MM 4096
#define FF 64
#define KK 16
#define BM (BB * MM)        // 16384 queries total

// Scan configuration: R queries per warp, 16 warps per block
#define R 2
#define WARPS 16
#define TPB (WARPS * 32)        // 512
#define QPB (WARPS * R)         // 32 queries per block
#define TILE 2048               // points per smem tile (32 KB of float4)

#define MIN_SIGMA_C 0.0001f
#define FLTMAX 3.402823466e+38f

// -------- static device scratch (no allocations allowed) --------
__device__ float g_featT[(size_t)BB * NN * FF];   // transposed features (B, N, F)

// ================= Kernel 1: feature transpose (B,F,N) -> (B,N,F) =================
__global__ void transpose_kernel(const float* __restrict__ feat) {
    __shared__ float tile[32][33];
    int b  = blockIdx.z;
    int f0 = blockIdx.y * 32;
    int n0 = blockIdx.x * 32;
    int tx = threadIdx.x, ty = threadIdx.y;   // block (32, 8)
#pragma unroll
    for (int i = ty; i < 32; i += 8)
        tile[i][tx] = feat[((size_t)b * FF + (f0 + i)) * NN + n0 + tx];
    __syncthreads();
#pragma unroll
    for (int i = ty; i < 32; i += 8)
        g_featT[((size_t)b * NN + (n0 + i)) * FF + f0 + tx] = tile[tx][i];
}

// ================= Kernel 2: fused R-query-per-warp top-16 + softmax + outputs =====
// grid: (MM/QPB, BB), block 512. Warp w owns queries m0 + w*R .. +R-1.
// Sorted ascending list per query distributed across lanes 0..15 (lane l = slot l).
// score = |p|^2 - 2 q.p  (monotone in d2 for fixed q -> valid for selection)
__global__ __launch_bounds__(TPB, 3)
void fused_kernel(const float* __restrict__ pc, const float* __restrict__ qc,
                  const float* __restrict__ temp, float* __restrict__ out) {
    __shared__ union SU {
        float4 spts[TILE];                          // 32 KB, scan phase
        struct {
            float sfeat[QPB][FF + 2];               // padded: aligned float2, low conflicts
            float spp[QPB][4];
        } ep;                                       // ~8.9 KB, epilogue phase
    } sm;

    const int tid  = threadIdx.x;
    const int lane = tid & 31;
    const int w    = tid >> 5;
    const int b    = blockIdx.y;
    const int m0   = blockIdx.x * QPB;
    const int mw   = m0 + w * R;                    // warp's first query

    const float* pcb = pc + (size_t)b * 3 * NN;
    const float* qcb = qc + (size_t)b * 3 * MM;

    float qx2[R], qy2[R], qz2[R];
#pragma unroll
    for (int r = 0; r < R; ++r) {
        qx2[r] = -2.0f * qcb[mw + r];
        qy2[r] = -2.0f * qcb[MM + mw + r];
        qz2[r] = -2.0f * qcb[2 * MM + mw + r];
    }

    float vs[R]; int vix[R]; float thr[R];
#pragma unroll
    for (int r = 0; r < R; ++r) { vs[r] = FLTMAX; vix[r] = 0; thr[r] = FLTMAX; }

    for (int tile = 0; tile < NN / TILE; ++tile) {
        const int n0 = tile * TILE;
        __syncthreads();
        for (int t = tid; t < TILE; t += TPB) {
            float x = pcb[n0 + t];
            float y = pcb[NN + n0 + t];
            float z = pcb[2 * NN + n0 + t];
            sm.spts[t] = make_float4(x, y, z, fmaf(x, x, fmaf(y, y, z * z)));
        }
        __syncthreads();

#pragma unroll 4
        for (int i = 0; i < TILE / 32; ++i) {
            float4 p = sm.spts[i * 32 + lane];      // one LDS.128 serves R queries
#pragma unroll
            for (int r = 0; r < R; ++r) {
                float sc = fmaf(p.x, qx2[r], fmaf(p.y, qy2[r], fmaf(p.z, qz2[r], p.w)));
                unsigned ball = __ballot_sync(0xffffffffu, sc < thr[r]);
                while (ball) {                      // candidates in ascending index order
                    int src = __ffs(ball) - 1;
                    ball &= ball - 1;
                    float v = __shfl_sync(0xffffffffu, sc, src);
                    if (v < thr[r]) {               // recheck vs tightened threshold
                        int vi = n0 + i * 32 + src;
                        float prev = __shfl_up_sync(0xffffffffu, vs[r], 1);
                        int  previ = __shfl_up_sync(0xffffffffu, vix[r], 1);
                        if (lane == 0) prev = -FLTMAX;
                        bool cprev = v < prev;      // shift from below
                        bool cm    = v < vs[r];     // insert at this slot
                        vix[r] = cprev ? previ : (cm ? vi : vix[r]);
                        vs[r]  = fminf(fmaxf(v, prev), vs[r]);
                        thr[r] = __shfl_sync(0xffffffffu, vs[r], 15);
                    }
                }
            }
        }
    }

    // ================= fused epilogue =================
    __syncthreads();                                // done with spts; overlay as ep
    const float tv = __ldg(temp);
    const float inv_sigma = 1.0f / fmaxf(tv * tv, MIN_SIGMA_C);
    const float* fbase = g_featT + (size_t)b * NN * FF;

#pragma unroll
    for (int r = 0; r < R; ++r) {
        const int q  = w * R + r;                   // block-local query id
        const int n  = vix[r];
        const float qx = -0.5f * qx2[r];            // exact recovery
        const float qy = -0.5f * qy2[r];
        const float qz = -0.5f * qz2[r];

        const float px = pcb[n], py = pcb[NN + n], pz = pcb[2 * NN + n];
        const float dx = px - qx, dy = py - qy, dz = pz - qz;
        const float d2 = fmaf(dx, dx, fmaf(dy, dy, dz * dz));

        float d2m = (lane < KK) ? d2 : FLTMAX;      // warp-min over 16 real slots
#pragma unroll
        for (int o = 16; o >= 1; o >>= 1) d2m = fminf(d2m, __shfl_xor_sync(0xffffffffu, d2m, o));

        float wgt = (lane < KK) ? __expf((d2m - d2) * inv_sigma) : 0.0f;
        float wsum = wgt;
#pragma unroll
        for (int o = 16; o >= 1; o >>= 1) wsum += __shfl_xor_sync(0xffffffffu, wsum, o);
        wgt *= 1.0f / wsum;

        // projected point
        float sx = wgt * px, sy = wgt * py, sz = wgt * pz;
#pragma unroll
        for (int o = 16; o >= 1; o >>= 1) {
            sx += __shfl_xor_sync(0xffffffffu, sx, o);
            sy += __shfl_xor_sync(0xffffffffu, sy, o);
            sz += __shfl_xor_sync(0xffffffffu, sz, o);
        }
        if (lane == 0) { sm.ep.spp[q][0] = sx; sm.ep.spp[q][1] = sy; sm.ep.spp[q][2] = sz; }

        // features: per neighbor j broadcast (w_j, n_j); 32 lanes load float2 (256B row)
        float ax = 0.0f, ay = 0.0f;
#pragma unroll
        for (int j = 0; j < KK; ++j) {
            float wj = __shfl_sync(0xffffffffu, wgt, j);
            int   nj = __shfl_sync(0xffffffffu, vix[r], j);
            float2 v = *reinterpret_cast<const float2*>(fbase + (size_t)nj * FF + 2 * lane);
            ax = fmaf(wj, v.x, ax);
            ay = fmaf(wj, v.y, ay);
        }
        *reinterpret_cast<float2*>(&sm.ep.sfeat[q][2 * lane]) = make_float2(ax, ay);
    }
    __syncthreads();

    // ---- coalesced block-wide stores (32 consecutive m per segment) ----
    if (tid < 3 * QPB) {                            // projected (B,3,M)
        int d = tid >> 5, ql = tid & 31;
        out[((size_t)b * 3 + d) * MM + m0 + ql] = sm.ep.spp[ql][d];
    }
    float* outf = out + (size_t)BB * 3 * MM;        // propagated (B,F,M)
#pragma unroll
    for (int rr = 0; rr < (QPB * FF) / TPB; ++rr) {
        int idx = rr * TPB + tid;
        int f = idx >> 5, ql = idx & 31;
        outf[((size_t)b * FF + f) * MM + m0 + ql] = sm.ep.sfeat[ql][f];
    }
}

// ================= launch =================
extern "C" void kernel_launch(void* const* d_in, const int* in_sizes, int n_in,
                              void* d_out, int out_size) {
    const float* point_cloud    = (const float*)d_in[0];  // (B, 3, N)
    const float* query_cloud    = (const float*)d_in[1];  // (B, 3, M)
    const float* point_features = (const float*)d_in[2];  // (B, F, N)
    const float* temperature    = (const float*)d_in[3];  // scalar
    float* out = (float*)d_out;  // [projected (B,3,M) | propagated (B,F,M)]

    (void)in_sizes; (void)n_in; (void)out_size;

    dim3 tgrid(NN / 32, FF / 32, BB);
    dim3 tblk(32, 8);
    transpose_kernel<<<tgrid, tblk>>>(point_features);

    dim3 sgrid(MM / QPB, BB);
    fused_kernel<<<sgrid, TPB>>>(point_cloud, query_cloud, temperature, (float*)d_out);
}

// round 8
// speedup vs baseline: 1.1217x; 1.1217x over previous
#include <cuda_runtime.h>
#include <cuda_bf16.h>
#include <cstdint>

// Problem constants (fixed shapes from reference setup_inputs)
#define BB 4
#define NN 8192
#define MM 4096
#define FF 64
#define KK 16
#define BM (BB * MM)        // 16384 queries total

// Scan configuration: R queries per warp, 8 warps per block, 2 points per lane/iter
#define R 2
#define WARPS 8
#define TPB (WARPS * 32)        // 256
#define QPB (WARPS * R)         // 16 queries per block
#define TILE 2048               // points per smem tile (32 KB of float4)
#define GRP 64                  // points per inner iteration (2 per lane)

#define MIN_SIGMA_C 0.0001f
#define FLTMAX 3.402823466e+38f

// -------- static device scratch (no allocations allowed) --------
__device__ float g_featT[(size_t)BB * NN * FF];   // transposed features (B, N, F)

// ================= Kernel 1: feature transpose (B,F,N) -> (B,N,F) =================
__global__ void transpose_kernel(const float* __restrict__ feat) {
    __shared__ float tile[32][33];
    int b  = blockIdx.z;
    int f0 = blockIdx.y * 32;
    int n0 = blockIdx.x * 32;
    int tx = threadIdx.x, ty = threadIdx.y;   // block (32, 8)
#pragma unroll
    for (int i = ty; i < 32; i += 8)
        tile[i][tx] = feat[((size_t)b * FF + (f0 + i)) * NN + n0 + tx];
    __syncthreads();
#pragma unroll
    for (int i = ty; i < 32; i += 8)
        g_featT[((size_t)b * NN + (n0 + i)) * FF + f0 + tx] = tile[tx][i];
}

// ================= Kernel 2: fused top-16 + softmax + outputs =====================
// grid: (MM/QPB, BB), block 256. Warp w owns queries m0 + w*R .. +R-1.
// Sorted ascending list per query distributed across lanes 0..15 (lane l = slot l).
// score = |p|^2 - 2 q.p  (monotone in d2 for fixed q -> valid for selection)
__global__ __launch_bounds__(TPB, 6)
void fused_kernel(const float* __restrict__ pc, const float* __restrict__ qc,
                  const float* __restrict__ temp, float* __restrict__ out) {
    __shared__ union SU {
        float4 spts[TILE];                          // 32 KB, scan phase
        struct {
            float sfeat[QPB][FF + 2];               // padded staging
            float spp[QPB][4];
        } ep;                                       // ~4.5 KB, epilogue phase
    } sm;

    const int tid  = threadIdx.x;
    const int lane = tid & 31;
    const int w    = tid >> 5;
    const int b    = blockIdx.y;
    const int m0   = blockIdx.x * QPB;
    const int mw   = m0 + w * R;                    // warp's first query

    const float* pcb = pc + (size_t)b * 3 * NN;
    const float* qcb = qc + (size_t)b * 3 * MM;

    float qx2[R], qy2[R], qz2[R];
#pragma unroll
    for (int r = 0; r < R; ++r) {
        qx2[r] = -2.0f * qcb[mw + r];
        qy2[r] = -2.0f * qcb[MM + mw + r];
        qz2[r] = -2.0f * qcb[2 * MM + mw + r];
    }

    float vs[R]; int vix[R]; float thr[R];
#pragma unroll
    for (int r = 0; r < R; ++r) { vs[r] = FLTMAX; vix[r] = 0; thr[r] = FLTMAX; }

    // fast insert: no recheck, no per-candidate thr update. No-op if v doesn't qualify.
#define FAST_INSERT(rr, v, vi)                                          \
    do {                                                                \
        float prev = __shfl_up_sync(0xffffffffu, vs[rr], 1);            \
        int  previ = __shfl_up_sync(0xffffffffu, vix[rr], 1);           \
        if (lane == 0) prev = -FLTMAX;                                  \
        bool cprev = (v) < prev;                                        \
        bool cm    = (v) < vs[rr];                                      \
        vix[rr] = cprev ? previ : (cm ? (vi) : vix[rr]);                \
        vs[rr]  = fminf(fmaxf((v), prev), vs[rr]);                      \
    } while (0)

    for (int tile = 0; tile < NN / TILE; ++tile) {
        const int n0 = tile * TILE;
        __syncthreads();
        for (int t = tid; t < TILE; t += TPB) {
            float x = pcb[n0 + t];
            float y = pcb[NN + n0 + t];
            float z = pcb[2 * NN + n0 + t];
            sm.spts[t] = make_float4(x, y, z, fmaf(x, x, fmaf(y, y, z * z)));
        }
        __syncthreads();

        int i0 = 0;
        if (tile == 0) {
            // ---- peeled first group: thr is wide open, use tightening inserts ----
            float4 pA = sm.spts[lane];
            float4 pB = sm.spts[32 + lane];
#pragma unroll
            for (int r = 0; r < R; ++r) {
#pragma unroll
                for (int ps = 0; ps < 2; ++ps) {
                    float4 p  = ps ? pB : pA;
                    int    nb = ps * 32;
                    float sc = fmaf(p.x, qx2[r], fmaf(p.y, qy2[r], fmaf(p.z, qz2[r], p.w)));
                    unsigned ball = __ballot_sync(0xffffffffu, sc < thr[r]);
                    while (ball) {
                        int src = __ffs(ball) - 1;
                        ball &= ball - 1;
                        float v = __shfl_sync(0xffffffffu, sc, src);
                        if (v < thr[r]) {
                            FAST_INSERT(r, v, nb + src);
                            thr[r] = __shfl_sync(0xffffffffu, vs[r], 15);
                        }
                    }
                }
            }
            i0 = 1;
        }

#pragma unroll 2
        for (int i = i0; i < TILE / GRP; ++i) {
            float4 pA = sm.spts[i * GRP + lane];        // one pair of LDS.128 serves R queries
            float4 pB = sm.spts[i * GRP + 32 + lane];
#pragma unroll
            for (int r = 0; r < R; ++r) {
                float scA = fmaf(pA.x, qx2[r], fmaf(pA.y, qy2[r], fmaf(pA.z, qz2[r], pA.w)));
                float scB = fmaf(pB.x, qx2[r], fmaf(pB.y, qy2[r], fmaf(pB.z, qz2[r], pB.w)));
                bool fA = scA < thr[r], fB = scB < thr[r];
                if (__ballot_sync(0xffffffffu, fA || fB)) {     // rare
                    const int base = n0 + i * GRP;
                    unsigned bA = __ballot_sync(0xffffffffu, fA);
                    while (bA) {                      // ascending index order
                        int src = __ffs(bA) - 1;
                        bA &= bA - 1;
                        float v = __shfl_sync(0xffffffffu, scA, src);
                        FAST_INSERT(r, v, base + src);
                    }
                    unsigned bB = __ballot_sync(0xffffffffu, fB);
                    while (bB) {
                        int src = __ffs(bB) - 1;
                        bB &= bB - 1;
                        float v = __shfl_sync(0xffffffffu, scB, src);
                        FAST_INSERT(r, v, base + 32 + src);
                    }
                    thr[r] = __shfl_sync(0xffffffffu, vs[r], 15);   // once per group
                }
            }
        }
    }

    // ================= fused epilogue =================
    __syncthreads();                                // done with spts; overlay as ep
    const float tv = __ldg(temp);
    const float inv_sigma = 1.0f / fmaxf(tv * tv, MIN_SIGMA_C);
    const float* fbase = g_featT + (size_t)b * NN * FF;

#pragma unroll
    for (int r = 0; r < R; ++r) {
        const int q  = w * R + r;                   // block-local query id
        const int n  = vix[r];
        const float qx = -0.5f * qx2[r];            // exact recovery
        const float qy = -0.5f * qy2[r];
        const float qz = -0.5f * qz2[r];

        const float px = pcb[n], py = pcb[NN + n], pz = pcb[2 * NN + n];
        const float dx = px - qx, dy = py - qy, dz = pz - qz;
        const float d2 = fmaf(dx, dx, fmaf(dy, dy, dz * dz));

        float d2m = (lane < KK) ? d2 : FLTMAX;      // warp-min over 16 real slots
#pragma unroll
        for (int o = 16; o >= 1; o >>= 1) d2m = fminf(d2m, __shfl_xor_sync(0xffffffffu, d2m, o));

        float wgt = (lane < KK) ? __expf((d2m - d2) * inv_sigma) : 0.0f;
        float wsum = wgt;
#pragma unroll
        for (int o = 16; o >= 1; o >>= 1) wsum += __shfl_xor_sync(0xffffffffu, wsum, o);
        wgt *= 1.0f / wsum;

        // projected point
        float sx = wgt * px, sy = wgt * py, sz = wgt * pz;
#pragma unroll
        for (int o = 16; o >= 1; o >>= 1) {
            sx += __shfl_xor_sync(0xffffffffu, sx, o);
            sy += __shfl_xor_sync(0xffffffffu, sy, o);
            sz += __shfl_xor_sync(0xffffffffu, sz, o);
        }
        if (lane == 0) { sm.ep.spp[q][0] = sx; sm.ep.spp[q][1] = sy; sm.ep.spp[q][2] = sz; }

        // features: per neighbor j broadcast (w_j, n_j); 32 lanes load float2 (256B row)
        float ax = 0.0f, ay = 0.0f;
#pragma unroll
        for (int j = 0; j < KK; ++j) {
            float wj = __shfl_sync(0xffffffffu, wgt, j);
            int   nj = __shfl_sync(0xffffffffu, vix[r], j);
            float2 v = *reinterpret_cast<const float2*>(fbase + (size_t)nj * FF + 2 * lane);
            ax = fmaf(wj, v.x, ax);
            ay = fmaf(wj, v.y, ay);
        }
        *reinterpret_cast<float2*>(&sm.ep.sfeat[q][2 * lane]) = make_float2(ax, ay);
    }
    __syncthreads();

    // ---- coalesced block-wide stores (16 consecutive m per segment) ----
    if (tid < 3 * QPB) {                            // projected (B,3,M)
        int d = tid >> 4, ql = tid & 15;
        out[((size_t)b * 3 + d) * MM + m0 + ql] = sm.ep.spp[ql][d];
    }
    float* outf = out + (size_t)BB * 3 * MM;        // propagated (B,F,M)
#pragma unroll
    for (int rr = 0; rr < (QPB * FF) / TPB; ++rr) {
        int idx = rr * TPB + tid;
        int f = idx >> 4, ql = idx & 15;
        outf[((size_t)b * FF + f) * MM + m0 + ql] = sm.ep.sfeat[ql][f];
    }
#undef FAST_INSERT
}

// ================= launch =================
extern "C" void kernel_launch(void* const* d_in, const int* in_sizes, int n_in,
                              void* d_out, int out_size) {
    const float* point_cloud    = (const float*)d_in[0];  // (B, 3, N)
    const float* query_cloud    = (const float*)d_in[1];  // (B, 3, M)
    const float* point_features = (const float*)d_in[2];  // (B, F, N)
    const float* temperature    = (const float*)d_in[3];  // scalar
    float* out = (float*)d_out;  // [projected (B,3,M) | propagated (B,F,M)]

    (void)in_sizes; (void)n_in; (void)out_size;

    dim3 tgrid(NN / 32, FF / 32, BB);
    dim3 tblk(32, 8);
    transpose_kernel<<<tgrid, tblk>>>(point_features);

    dim3 sgrid(MM / QPB, BB);
    fused_kernel<<<sgrid, TPB>>>(point_cloud, query_cloud, temperature, (float*)d_out);
}